// round 2
// baseline (speedup 1.0000x reference)
#include <cuda_runtime.h>

// ---------------------------------------------------------------------------
// DctLayer: out_c = P_r * B * P_s^T per 8x8 block, where P_low is the rank-4
// DCT low-pass projector and P_high = I - P_low. Corner masks are separable,
// so the whole forward-DCT/mask/inverse-DCT pipeline reduces to 3 tiny 8x8
// matmuls + 3 subtractions per block. Pure HBM-bandwidth problem (~503 MB).
//
// L = P_low has DCT symmetry: r = L*a decomposes into butterfly + two 4x4
// matvecs with constant matrices:
//   E[i][x] = 0.125 + 0.25*g[i]*g[x],          g  = [c2, c6, -c6, -c2]
//   O[i][x] = 0.25*(h1[i]h1[x] + h3[i]h3[x]),  h1 = [c1,c3,c5,c7], h3 = [c3,-c7,-c1,-c5]
// (cm = cos(m*pi/16)). Constants verified numerically; trace(L)=4, L*1=1.
// ---------------------------------------------------------------------------

#define E00 0.33838834764831845f
#define E01 0.21338834764831843f
#define E02 0.03661165235168157f
#define E03 (-0.08838834764831845f)
#define E11 0.16161165235168156f
#define E12 0.08838834764831844f
#define E13 0.03661165235168157f
#define E22 0.16161165235168156f
#define E23 0.21338834764831843f
#define E33 0.33838834764831845f

#define O00 0.41332037060954707f
#define O01 0.16332037060954707f
#define O02 (-0.06764951251827464f)
#define O03 (-0.06764951251827464f)
#define O11 0.18235048748172537f
#define O12 0.16332037060954707f
#define O13 0.06764951251827464f
#define O22 0.31764951251827466f
#define O23 0.16332037060954707f
#define O33 0.08667962939045293f

// r = L * a for an 8-vector a. Butterfly + two 4x4 matvecs.
// Coefficients are compile-time literals -> FFMA-imm form (rt_SMSP = 1).
__device__ __forceinline__ void lmix8(const float a[8], float r[8]) {
    float s0 = a[0] + a[7], s1 = a[1] + a[6], s2 = a[2] + a[5], s3 = a[3] + a[4];
    float d0 = a[0] - a[7], d1 = a[1] - a[6], d2 = a[2] - a[5], d3 = a[3] - a[4];

    float e0 = E00 * s0 + E01 * s1 + E02 * s2 + E03 * s3;
    float e1 = E01 * s0 + E11 * s1 + E12 * s2 + E13 * s3;
    float e2 = E02 * s0 + E12 * s1 + E22 * s2 + E23 * s3;
    float e3 = E03 * s0 + E13 * s1 + E23 * s2 + E33 * s3;

    float o0 = O00 * d0 + O01 * d1 + O02 * d2 + O03 * d3;
    float o1 = O01 * d0 + O11 * d1 + O12 * d2 + O13 * d3;
    float o2 = O02 * d0 + O12 * d1 + O22 * d2 + O23 * d3;
    float o3 = O03 * d0 + O13 * d1 + O23 * d2 + O33 * d3;

    r[0] = e0 + o0;  r[7] = e0 - o0;
    r[1] = e1 + o1;  r[6] = e1 - o1;
    r[2] = e2 + o2;  r[5] = e2 - o2;
    r[3] = e3 + o3;  r[4] = e3 - o3;
}

// One thread per 8x8 block. 96 channels * 64 * 64 blocks = 393216 threads.
__global__ void __launch_bounds__(256, 1)
dct_corner_kernel(const float* __restrict__ x, float* __restrict__ out)
{
    int g  = blockIdx.x * 256 + threadIdx.x;
    int bx = g & 63;          // block column (0..63)
    int tt = g >> 6;
    int by = tt & 63;         // block row    (0..63)
    int ch = tt >> 6;         // channel      (0..95)

    const float* src = x + ((size_t)ch << 18) + ((size_t)(by << 3) << 9) + (bx << 3);

    // Load the 8x8 block: 2 x float4 per row (adjacent threads cover adjacent
    // 32B chunks; each 128B line fully consumed across the instruction pair).
    float B[8][8];
#pragma unroll
    for (int r = 0; r < 8; ++r) {
        float4 v0 = __ldg((const float4*)(src + (size_t)r * 512));
        float4 v1 = __ldg((const float4*)(src + (size_t)r * 512 + 4));
        B[r][0] = v0.x; B[r][1] = v0.y; B[r][2] = v0.z; B[r][3] = v0.w;
        B[r][4] = v1.x; B[r][5] = v1.y; B[r][6] = v1.z; B[r][7] = v1.w;
    }

    // Vertical stage: R0 = L * B (mix rows, per column), R1 = B - R0 (in place).
    float R0[8][8];
#pragma unroll
    for (int j = 0; j < 8; ++j) {
        float a[8], r[8];
#pragma unroll
        for (int k = 0; k < 8; ++k) a[k] = B[k][j];
        lmix8(a, r);
#pragma unroll
        for (int i = 0; i < 8; ++i) R0[i][j] = r[i];
    }
#pragma unroll
    for (int i = 0; i < 8; ++i)
#pragma unroll
        for (int j = 0; j < 8; ++j) B[i][j] -= R0[i][j];   // B now holds R1

    // Horizontal stage per row + streamed float4 stores to the 4 output planes.
    const size_t PL = (size_t)96 * 512 * 512;              // plane stride (elements)
    float* o0 = out + ((size_t)ch << 18) + ((size_t)(by << 3) << 9) + (bx << 3);

#pragma unroll
    for (int i = 0; i < 8; ++i) {
        float t[8], u[8];
        float* p = o0 + (size_t)i * 512;

        lmix8(R0[i], t);                                   // out0 row = R0 * L^T
#pragma unroll
        for (int j = 0; j < 8; ++j) u[j] = R0[i][j] - t[j]; // out1 row
        *(float4*)(p)          = make_float4(t[0], t[1], t[2], t[3]);
        *(float4*)(p + 4)      = make_float4(t[4], t[5], t[6], t[7]);
        *(float4*)(p + PL)     = make_float4(u[0], u[1], u[2], u[3]);
        *(float4*)(p + PL + 4) = make_float4(u[4], u[5], u[6], u[7]);

        lmix8(B[i], t);                                    // out2 row = R1 * L^T
#pragma unroll
        for (int j = 0; j < 8; ++j) u[j] = B[i][j] - t[j];  // out3 row
        *(float4*)(p + 2 * PL)     = make_float4(t[0], t[1], t[2], t[3]);
        *(float4*)(p + 2 * PL + 4) = make_float4(t[4], t[5], t[6], t[7]);
        *(float4*)(p + 3 * PL)     = make_float4(u[0], u[1], u[2], u[3]);
        *(float4*)(p + 3 * PL + 4) = make_float4(u[4], u[5], u[6], u[7]);
    }
}

extern "C" void kernel_launch(void* const* d_in, const int* in_sizes, int n_in,
                              void* d_out, int out_size) {
    const float* x = (const float*)d_in[0];
    float* out     = (float*)d_out;

    // total 8x8 blocks = elements / 64 ; one thread per block
    int total_threads = in_sizes[0] / 64;          // 393216
    int grid = (total_threads + 255) / 256;        // 1536
    dct_corner_kernel<<<grid, 256>>>(x, out);
}